// round 14
// baseline (speedup 1.0000x reference)
#include <cuda_runtime.h>
#include <cstdint>

// Problem constants (B=16, N=325, H=8, L=24, DK=DV=64)
#define L_    24
#define DV_   64
#define NT_   41600
#define QK_   1536                /* floats per Q/K/V tile */
#define MS_   576                 /* floats per mask/res/scores tile */

#define SQ    68                  /* Q stage stride: qg*6*68 = {0,24,16,8} mod 32 */
#define SK    72                  /* K stage stride: kg*3*72 = {0,24,16,8} mod 32 */
#define SS    24                  /* raw scores: natural stride (contiguous) */
#define SA    28                  /* attn stride (bank-perfect f4 reads) */
#define TPC   8                   /* tiles per CTA */
#define OFF_K 1632                /* Q = 24*68 */
#define OFF_M 3360                /* + K = 24*72 */
#define OFF_R 3936
#define STGF  4512                /* floats per stage */

static const long long CTX_ELEMS = (long long)NT_ * QK_;   // 63,897,600

__device__ __forceinline__ void cpa16(uint32_t s, const float4* g) {
    asm volatile("cp.async.cg.shared.global [%0], [%1], 16;" :: "r"(s), "l"(g));
}

// packed dual-FMA
__device__ __forceinline__ unsigned long long ffma2(unsigned long long a,
                                                    unsigned long long b,
                                                    unsigned long long c) {
    unsigned long long d;
    asm("fma.rn.f32x2 %0, %1, %2, %3;" : "=l"(d) : "l"(a), "l"(b), "l"(c));
    return d;
}
__device__ __forceinline__ unsigned long long dup2(float x) {
    unsigned long long d;
    asm("mov.b64 %0, {%1, %1};" : "=l"(d) : "f"(x));
    return d;
}
__device__ __forceinline__ float lo32(unsigned long long v) {
    return __uint_as_float((unsigned)(v & 0xffffffffu));
}
__device__ __forceinline__ float hi32(unsigned long long v) {
    return __uint_as_float((unsigned)(v >> 32));
}

union F4U { float4 f; unsigned long long u[2]; };

__global__ __launch_bounds__(128, 5)
void satt_kernel(const float* __restrict__ Qg, const float* __restrict__ Kg,
                 const float* __restrict__ Vg, const float* __restrict__ Mg,
                 const float* __restrict__ Rg,
                 float* __restrict__ Cg, float* __restrict__ Sg)
{
    __shared__ float smem[2 * STGF + 2 * (L_ * SS) + 2 * (L_ * SA)];   // 46080 B
    float* const sSb = smem + 2 * STGF;                 // 2 x 576  raw scores
    float* const sAb = sSb + 2 * (L_ * SS);             // 2 x 672  normalized attn
    const uint32_t sb = (uint32_t)__cvta_generic_to_shared(smem);

    const int tid   = threadIdx.x;
    const int lane  = tid & 31;
    const int wid   = tid >> 5;
    const int role  = wid ^ ((int)blockIdx.x & 3);      // 0,1: QK+softmax; 2,3: store+AV
    const int tile0 = blockIdx.x * TPC;

    auto issue = [&](int buf, int tile) {
        const uint32_t b = sb + buf * (STGF * 4);
        const float4* Q4 = reinterpret_cast<const float4*>(Qg + (size_t)tile * QK_);
        const float4* K4 = reinterpret_cast<const float4*>(Kg + (size_t)tile * QK_);
#pragma unroll
        for (int it = 0; it < 3; ++it) {
            int e = tid + it * 128;                     // f4 index 0..383
            int q = e >> 4, d = (e & 15) << 2;
            cpa16(b + (uint32_t)(q * SQ + d) * 4, Q4 + e);
            cpa16(b + (uint32_t)(OFF_K + q * SK + d) * 4, K4 + e);
        }
        const float4* M4 = reinterpret_cast<const float4*>(Mg + (size_t)tile * MS_);
        const float4* R4 = reinterpret_cast<const float4*>(Rg + (size_t)tile * MS_);
        cpa16(b + (uint32_t)(OFF_M + tid * 4) * 4, M4 + tid);
        cpa16(b + (uint32_t)(OFF_R + tid * 4) * 4, R4 + tid);
        if (tid < 16) {
            cpa16(b + (uint32_t)(OFF_M + (128 + tid) * 4) * 4, M4 + 128 + tid);
            cpa16(b + (uint32_t)(OFF_R + (128 + tid) * 4) * 4, R4 + 128 + tid);
        }
        asm volatile("cp.async.commit_group;");
    };

    issue(0, tile0);                                    // group for tile 0 in flight

    for (int t = 0; t <= TPC; ++t) {
        // group for tile t was issued a full step ago -> wait is a landed no-op
        asm volatile("cp.async.wait_group 0;");
        __syncthreads();        // publishes stage[t]; closes prev reads of sS/sA[t&1] and stage[(t+1)&1]
        if (t + 1 < TPC) issue((t + 1) & 1, tile0 + t + 1);

        // -------- producer: QK^T (LDS.64, d-parity, f32x2) + epilogue + softmax --------
        if (t < TPC && role < 2) {
            const int buf = t & 1;
            const float* const bQ = smem + buf * STGF;
            const float* const bK = bQ + OFF_K;
            const float* const bM = bQ + OFF_M;
            const float* const bR = bQ + OFF_R;
            float* const sS = sSb + buf * (L_ * SS);
            float* const sA = sAb + buf * (L_ * SA);

            const int dq = lane & 1;                    // d-parity (pairs)
            const int kg = (lane >> 1) & 3;             // 4 k-groups of 3
            const int qg = lane >> 3;                   // 4 q-groups of 6
            const int q0 = qg * 6;
            const int k0 = role * 12 + kg * 3;

            unsigned long long acc2[6][3] = {};
            const float* Qp = bQ + q0 * SQ + (dq << 1);
            const float* Kp = bK + k0 * SK + (dq << 1);
#pragma unroll
            for (int s = 0; s < 16; ++s) {
                const int d = s << 2;
                unsigned long long qv[6], kv[3];
#pragma unroll
                for (int i = 0; i < 6; ++i)
                    qv[i] = *reinterpret_cast<const unsigned long long*>(Qp + i * SQ + d);
#pragma unroll
                for (int j = 0; j < 3; ++j)
                    kv[j] = *reinterpret_cast<const unsigned long long*>(Kp + j * SK + d);
#pragma unroll
                for (int i = 0; i < 6; ++i)
#pragma unroll
                    for (int j = 0; j < 3; ++j)
                        acc2[i][j] = ffma2(qv[i], kv[j], acc2[i][j]);
            }
            // fold packed pairs -> scalar, combine d-parity halves across XOR-1 lanes
            float full[6][3];
#pragma unroll
            for (int i = 0; i < 6; ++i)
#pragma unroll
                for (int j = 0; j < 3; ++j) {
                    float f = lo32(acc2[i][j]) + hi32(acc2[i][j]);
                    full[i][j] = f + __shfl_xor_sync(0xffffffffu, f, 1);
                }
            // each parity lane owns 3 q rows
            const int qr = q0 + dq * 3;
            float v[3][3];
#pragma unroll
            for (int ii = 0; ii < 3; ++ii)
#pragma unroll
                for (int j = 0; j < 3; ++j)
                    v[ii][j] = dq ? full[ii + 3][j] : full[ii][j];

            // epilogue: scale + res + mask; raw scores -> sS (natural layout)
#pragma unroll
            for (int ii = 0; ii < 3; ++ii)
#pragma unroll
                for (int j = 0; j < 3; ++j) {
                    const int idx = (qr + ii) * L_ + k0 + j;
                    float s = fmaf(v[ii][j], 0.125f, bR[idx]);
                    if (bM[idx] > 0.5f) s = -1e9f;
                    v[ii][j] = s;
                    sS[idx] = s;
                }
            // softmax over q: butterfly over dq (XOR1) and qg (XOR8, XOR16)
#pragma unroll
            for (int j = 0; j < 3; ++j) {
                float m = fmaxf(fmaxf(v[0][j], v[1][j]), v[2][j]);
                m = fmaxf(m, __shfl_xor_sync(0xffffffffu, m, 1));
                m = fmaxf(m, __shfl_xor_sync(0xffffffffu, m, 8));
                m = fmaxf(m, __shfl_xor_sync(0xffffffffu, m, 16));
                float s = 0.0f;
#pragma unroll
                for (int ii = 0; ii < 3; ++ii) {
                    v[ii][j] = __expf(v[ii][j] - m);
                    s += v[ii][j];
                }
                s += __shfl_xor_sync(0xffffffffu, s, 1);
                s += __shfl_xor_sync(0xffffffffu, s, 8);
                s += __shfl_xor_sync(0xffffffffu, s, 16);
                const float r = __fdividef(1.0f, s);
#pragma unroll
                for (int ii = 0; ii < 3; ++ii)
                    sA[(qr + ii) * SA + k0 + j] = v[ii][j] * r;
            }
        }

        // -------- consumer: prefetch V[t]; score store + C = A·V for tile t-1 --------
        if (role >= 2) {
            const int hw = ((role - 2) << 5) | lane;        // 0..63

            // L1-warm the V tile consumed NEXT step (48 x 128B lines)
            if (t < TPC && hw < 48) {
                const float* p = Vg + (size_t)(tile0 + t) * QK_ + hw * 32;
                asm volatile("prefetch.global.L1 [%0];" :: "l"(p));
            }

            if (t > 0) {
                const int pb   = (t - 1) & 1;
                const int tile = tile0 + t - 1;
                const float* const sS = sSb + pb * (L_ * SS);
                const float* const sA = sAb + pb * (L_ * SA);

                // raw masked scores -> global: contiguous float4 copy
                {
                    const float4* s4 = reinterpret_cast<const float4*>(sS);
                    float4* S4 = reinterpret_cast<float4*>(Sg + (size_t)tile * MS_);
                    S4[hw]      = s4[hw];
                    S4[hw + 64] = s4[hw + 64];
                    if (hw < 16) S4[hw + 128] = s4[hw + 128];
                }

                // A·V: this warp owns 8 f4 v-columns; TQ=3, packed dual-FMA over v
                {
                    const int q0 = (lane >> 2) * 3;
                    const int c0 = ((role - 2) << 3) + ((lane & 3) << 1);   // f4 col, 2 per lane
                    const float4* V4 = reinterpret_cast<const float4*>(Vg + (size_t)tile * QK_);
                    unsigned long long c2[3][4] = {};       // 3 q-rows x 4 v-pairs (8 v-cols)
#pragma unroll
                    for (int kc = 0; kc < L_; kc += 4) {
                        float4 a[3];
#pragma unroll
                        for (int i = 0; i < 3; ++i)
                            a[i] = *reinterpret_cast<const float4*>(&sA[(q0 + i) * SA + kc]);
                        F4U v0[4], v1[4];
#pragma unroll
                        for (int m = 0; m < 4; ++m) {
                            v0[m].f = V4[(kc + m) * 16 + c0];
                            v1[m].f = V4[(kc + m) * 16 + c0 + 1];
                        }
#pragma unroll
                        for (int i = 0; i < 3; ++i) {
                            const float as[4] = { a[i].x, a[i].y, a[i].z, a[i].w };
#pragma unroll
                            for (int m = 0; m < 4; ++m) {
                                const unsigned long long ad = dup2(as[m]);
                                c2[i][0] = ffma2(ad, v0[m].u[0], c2[i][0]);
                                c2[i][1] = ffma2(ad, v0[m].u[1], c2[i][1]);
                                c2[i][2] = ffma2(ad, v1[m].u[0], c2[i][2]);
                                c2[i][3] = ffma2(ad, v1[m].u[1], c2[i][3]);
                            }
                        }
                    }
                    float* C = Cg + (size_t)tile * QK_;
#pragma unroll
                    for (int i = 0; i < 3; ++i) {
                        F4U o0, o1;
                        o0.u[0] = c2[i][0]; o0.u[1] = c2[i][1];
                        o1.u[0] = c2[i][2]; o1.u[1] = c2[i][3];
                        *reinterpret_cast<float4*>(&C[(q0 + i) * DV_ + (c0 << 2)])     = o0.f;
                        *reinterpret_cast<float4*>(&C[(q0 + i) * DV_ + (c0 << 2) + 4]) = o1.f;
                    }
                }
            }
        }
    }
}

extern "C" void kernel_launch(void* const* d_in, const int* in_sizes, int n_in,
                              void* d_out, int out_size)
{
    (void)in_sizes; (void)n_in; (void)out_size;
    const float* Q  = (const float*)d_in[0];
    const float* K  = (const float*)d_in[1];
    const float* V  = (const float*)d_in[2];
    const float* Mm = (const float*)d_in[3];
    const float* Ra = (const float*)d_in[4];
    float* ctx    = (float*)d_out;                 // (context, scores) concatenated
    float* scores = (float*)d_out + CTX_ELEMS;
    satt_kernel<<<NT_ / TPC, 128>>>(Q, K, V, Mm, Ra, ctx, scores);
}

// round 15
// speedup vs baseline: 1.0582x; 1.0582x over previous
#include <cuda_runtime.h>
#include <cstdint>

// Problem constants (B=16, N=325, H=8, L=24, DK=DV=64)
#define L_    24
#define DV_   64
#define NT_   41600
#define QK_   1536                /* floats per Q/K/V tile */
#define MS_   576                 /* floats per mask/res/scores tile */

#define SQ    68                  /* Q stage stride: qg*6*68 = {0,24,16,8} mod 32 */
#define SK    68                  /* K stage stride: kg*3*68 = {0,12,24,4} mod 32 -> conflict-free */
#define SS    24                  /* raw scores: natural stride (contiguous) */
#define SA    28                  /* attn stride (bank-perfect f4 reads) */
#define TPC   8                   /* tiles per CTA */
#define OFF_K 1632                /* Q = 24*68 */
#define OFF_M 3264                /* + K = 24*68 */
#define OFF_R 3840
#define STGF  4416                /* floats per stage */

static const long long CTX_ELEMS = (long long)NT_ * QK_;   // 63,897,600

__device__ __forceinline__ void cpa16(uint32_t s, const float4* g) {
    asm volatile("cp.async.cg.shared.global [%0], [%1], 16;" :: "r"(s), "l"(g));
}

// packed dual-FMA
__device__ __forceinline__ unsigned long long ffma2(unsigned long long a,
                                                    unsigned long long b,
                                                    unsigned long long c) {
    unsigned long long d;
    asm("fma.rn.f32x2 %0, %1, %2, %3;" : "=l"(d) : "l"(a), "l"(b), "l"(c));
    return d;
}
__device__ __forceinline__ unsigned long long dup2(float x) {
    unsigned long long d;
    asm("mov.b64 %0, {%1, %1};" : "=l"(d) : "f"(x));
    return d;
}
__device__ __forceinline__ float lo32(unsigned long long v) {
    return __uint_as_float((unsigned)(v & 0xffffffffu));
}
__device__ __forceinline__ float hi32(unsigned long long v) {
    return __uint_as_float((unsigned)(v >> 32));
}

union F4U { float4 f; unsigned long long u[2]; };

__global__ __launch_bounds__(128, 5)
void satt_kernel(const float* __restrict__ Qg, const float* __restrict__ Kg,
                 const float* __restrict__ Vg, const float* __restrict__ Mg,
                 const float* __restrict__ Rg,
                 float* __restrict__ Cg, float* __restrict__ Sg)
{
    __shared__ float smem[2 * STGF + 2 * (L_ * SS) + 2 * (L_ * SA)];   // 45312 B -> 5 CTAs/SM
    float* const sSb = smem + 2 * STGF;                 // 2 x 576  raw scores
    float* const sAb = sSb + 2 * (L_ * SS);             // 2 x 672  normalized attn
    const uint32_t sb = (uint32_t)__cvta_generic_to_shared(smem);

    const int tid   = threadIdx.x;
    const int lane  = tid & 31;
    const int wid   = tid >> 5;
    const int role  = wid ^ ((int)blockIdx.x & 3);      // 0,1: QK+softmax; 2,3: store+AV
    const int tile0 = blockIdx.x * TPC;

    auto issue = [&](int buf, int tile) {
        const uint32_t b = sb + buf * (STGF * 4);
        const float4* Q4 = reinterpret_cast<const float4*>(Qg + (size_t)tile * QK_);
        const float4* K4 = reinterpret_cast<const float4*>(Kg + (size_t)tile * QK_);
#pragma unroll
        for (int it = 0; it < 3; ++it) {
            int e = tid + it * 128;                     // f4 index 0..383
            int q = e >> 4, d = (e & 15) << 2;
            cpa16(b + (uint32_t)(q * SQ + d) * 4, Q4 + e);
            cpa16(b + (uint32_t)(OFF_K + q * SK + d) * 4, K4 + e);
        }
        const float4* M4 = reinterpret_cast<const float4*>(Mg + (size_t)tile * MS_);
        const float4* R4 = reinterpret_cast<const float4*>(Rg + (size_t)tile * MS_);
        cpa16(b + (uint32_t)(OFF_M + tid * 4) * 4, M4 + tid);
        cpa16(b + (uint32_t)(OFF_R + tid * 4) * 4, R4 + tid);
        if (tid < 16) {
            cpa16(b + (uint32_t)(OFF_M + (128 + tid) * 4) * 4, M4 + 128 + tid);
            cpa16(b + (uint32_t)(OFF_R + (128 + tid) * 4) * 4, R4 + 128 + tid);
        }
        asm volatile("cp.async.commit_group;");
    };

    issue(0, tile0);                                    // group for tile 0 in flight

    for (int t = 0; t <= TPC; ++t) {
        // group for tile t was issued a full step ago -> wait is a landed no-op
        asm volatile("cp.async.wait_group 0;");
        __syncthreads();        // publishes stage[t]; closes prev reads of sS/sA[t&1] and stage[(t+1)&1]
        if (t + 1 < TPC) issue((t + 1) & 1, tile0 + t + 1);

        // -------- producer: QK^T (LDS.64, d-parity, f32x2) + epilogue + softmax --------
        if (t < TPC && role < 2) {
            const int buf = t & 1;
            const float* const bQ = smem + buf * STGF;
            const float* const bK = bQ + OFF_K;
            const float* const bM = bQ + OFF_M;
            const float* const bR = bQ + OFF_R;
            float* const sS = sSb + buf * (L_ * SS);
            float* const sA = sAb + buf * (L_ * SA);

            const int dq = lane & 1;                    // d-parity (pairs)
            const int kg = (lane >> 1) & 3;             // 4 k-groups of 3
            const int qg = lane >> 3;                   // 4 q-groups of 6
            const int q0 = qg * 6;
            const int k0 = role * 12 + kg * 3;

            unsigned long long acc2[6][3] = {};
            const float* Qp = bQ + q0 * SQ + (dq << 1);
            const float* Kp = bK + k0 * SK + (dq << 1);
#pragma unroll
            for (int s = 0; s < 16; ++s) {
                const int d = s << 2;
                unsigned long long qv[6], kv[3];
#pragma unroll
                for (int i = 0; i < 6; ++i)
                    qv[i] = *reinterpret_cast<const unsigned long long*>(Qp + i * SQ + d);
#pragma unroll
                for (int j = 0; j < 3; ++j)
                    kv[j] = *reinterpret_cast<const unsigned long long*>(Kp + j * SK + d);
#pragma unroll
                for (int i = 0; i < 6; ++i)
#pragma unroll
                    for (int j = 0; j < 3; ++j)
                        acc2[i][j] = ffma2(qv[i], kv[j], acc2[i][j]);
            }
            // fold packed pairs -> scalar, combine d-parity halves across XOR-1 lanes
            float full[6][3];
#pragma unroll
            for (int i = 0; i < 6; ++i)
#pragma unroll
                for (int j = 0; j < 3; ++j) {
                    float f = lo32(acc2[i][j]) + hi32(acc2[i][j]);
                    full[i][j] = f + __shfl_xor_sync(0xffffffffu, f, 1);
                }
            // each parity lane owns 3 q rows
            const int qr = q0 + dq * 3;
            float v[3][3];
#pragma unroll
            for (int ii = 0; ii < 3; ++ii)
#pragma unroll
                for (int j = 0; j < 3; ++j)
                    v[ii][j] = dq ? full[ii + 3][j] : full[ii][j];

            // epilogue: scale + res + mask; raw scores -> sS (natural layout)
#pragma unroll
            for (int ii = 0; ii < 3; ++ii)
#pragma unroll
                for (int j = 0; j < 3; ++j) {
                    const int idx = (qr + ii) * L_ + k0 + j;
                    float s = fmaf(v[ii][j], 0.125f, bR[idx]);
                    if (bM[idx] > 0.5f) s = -1e9f;
                    v[ii][j] = s;
                    sS[idx] = s;
                }
            // softmax over q: butterfly over dq (XOR1) and qg (XOR8, XOR16)
#pragma unroll
            for (int j = 0; j < 3; ++j) {
                float m = fmaxf(fmaxf(v[0][j], v[1][j]), v[2][j]);
                m = fmaxf(m, __shfl_xor_sync(0xffffffffu, m, 1));
                m = fmaxf(m, __shfl_xor_sync(0xffffffffu, m, 8));
                m = fmaxf(m, __shfl_xor_sync(0xffffffffu, m, 16));
                float s = 0.0f;
#pragma unroll
                for (int ii = 0; ii < 3; ++ii) {
                    v[ii][j] = __expf(v[ii][j] - m);
                    s += v[ii][j];
                }
                s += __shfl_xor_sync(0xffffffffu, s, 1);
                s += __shfl_xor_sync(0xffffffffu, s, 8);
                s += __shfl_xor_sync(0xffffffffu, s, 16);
                const float r = __fdividef(1.0f, s);
#pragma unroll
                for (int ii = 0; ii < 3; ++ii)
                    sA[(qr + ii) * SA + k0 + j] = v[ii][j] * r;
            }
        }

        // -------- consumer: prefetch V[t]; score store + C = A·V for tile t-1 --------
        if (role >= 2) {
            const int hw = ((role - 2) << 5) | lane;        // 0..63

            // L1-warm the V tile consumed NEXT step (48 x 128B lines)
            if (t < TPC && hw < 48) {
                const float* p = Vg + (size_t)(tile0 + t) * QK_ + hw * 32;
                asm volatile("prefetch.global.L1 [%0];" :: "l"(p));
            }

            if (t > 0) {
                const int pb   = (t - 1) & 1;
                const int tile = tile0 + t - 1;
                const float* const sS = sSb + pb * (L_ * SS);
                const float* const sA = sAb + pb * (L_ * SA);

                // raw masked scores -> global: contiguous float4 copy
                {
                    const float4* s4 = reinterpret_cast<const float4*>(sS);
                    float4* S4 = reinterpret_cast<float4*>(Sg + (size_t)tile * MS_);
                    S4[hw]      = s4[hw];
                    S4[hw + 64] = s4[hw + 64];
                    if (hw < 16) S4[hw + 128] = s4[hw + 128];
                }

                // A·V: this warp owns 8 f4 v-columns; TQ=3, packed dual-FMA over v
                {
                    const int q0 = (lane >> 2) * 3;
                    const int c0 = ((role - 2) << 3) + ((lane & 3) << 1);   // f4 col, 2 per lane
                    const float4* V4 = reinterpret_cast<const float4*>(Vg + (size_t)tile * QK_);
                    unsigned long long c2[3][4] = {};       // 3 q-rows x 4 v-pairs (8 v-cols)
#pragma unroll
                    for (int kc = 0; kc < L_; kc += 4) {
                        float4 a[3];
#pragma unroll
                        for (int i = 0; i < 3; ++i)
                            a[i] = *reinterpret_cast<const float4*>(&sA[(q0 + i) * SA + kc]);
                        F4U v0[4], v1[4];
#pragma unroll
                        for (int m = 0; m < 4; ++m) {
                            v0[m].f = V4[(kc + m) * 16 + c0];
                            v1[m].f = V4[(kc + m) * 16 + c0 + 1];
                        }
#pragma unroll
                        for (int i = 0; i < 3; ++i) {
                            const float as[4] = { a[i].x, a[i].y, a[i].z, a[i].w };
#pragma unroll
                            for (int m = 0; m < 4; ++m) {
                                const unsigned long long ad = dup2(as[m]);
                                c2[i][0] = ffma2(ad, v0[m].u[0], c2[i][0]);
                                c2[i][1] = ffma2(ad, v0[m].u[1], c2[i][1]);
                                c2[i][2] = ffma2(ad, v1[m].u[0], c2[i][2]);
                                c2[i][3] = ffma2(ad, v1[m].u[1], c2[i][3]);
                            }
                        }
                    }
                    float* C = Cg + (size_t)tile * QK_;
#pragma unroll
                    for (int i = 0; i < 3; ++i) {
                        F4U o0, o1;
                        o0.u[0] = c2[i][0]; o0.u[1] = c2[i][1];
                        o1.u[0] = c2[i][2]; o1.u[1] = c2[i][3];
                        *reinterpret_cast<float4*>(&C[(q0 + i) * DV_ + (c0 << 2)])     = o0.f;
                        *reinterpret_cast<float4*>(&C[(q0 + i) * DV_ + (c0 << 2) + 4]) = o1.f;
                    }
                }
            }
        }
    }
}

extern "C" void kernel_launch(void* const* d_in, const int* in_sizes, int n_in,
                              void* d_out, int out_size)
{
    (void)in_sizes; (void)n_in; (void)out_size;
    const float* Q  = (const float*)d_in[0];
    const float* K  = (const float*)d_in[1];
    const float* V  = (const float*)d_in[2];
    const float* Mm = (const float*)d_in[3];
    const float* Ra = (const float*)d_in[4];
    float* ctx    = (float*)d_out;                 // (context, scores) concatenated
    float* scores = (float*)d_out + CTX_ELEMS;
    satt_kernel<<<NT_ / TPC, 128>>>(Q, K, V, Mm, Ra, ctx, scores);
}